// round 7
// baseline (speedup 1.0000x reference)
#include <cuda_runtime.h>
#include <cuda_bf16.h>
#include <cstdint>

// Stage 0 (prep): c2 (fp32+fp64) per centroid + bf16 image of centroids in the
//   exact XOR-swizzled smem byte layout used by ldmatrix (row=n, 512B/row).
// Stage 1 (HMMA): per CTA of 128 rows, bf16 mma.sync GEMM D[128,256] = A.B^T,
//   s[k] = c2[k] - 2*dot -> per-row top-8 candidate indices (top-4 missed the
//   true second-max on exactly 1/262144 rows in R5 -> widened recall).
// Stage 2 (exact, validated R3): fp64 dots for the 8 candidates, replicate the
//   reference fp32 chain fl(sqrt(max(fl(fl(x2+c2)-fl(2xc)),0))), lower-index
//   tie-break; out[row] = centroids[second-max].

#define DIM  256
#define KTOT 256
#define NMAX 262144
#define NC   8          // candidates per row

__device__ float  g_c2[KTOT];
__device__ double g_c2d[KTOT];
__device__ int    g_cand[NMAX * NC];
__device__ unsigned long long g_centB[KTOT * DIM * 2 / 8];   // 128KB bf16 B image

__device__ __forceinline__ uint32_t smem_u32(const void* p) {
    uint32_t a;
    asm("{ .reg .u64 t; cvta.to.shared.u64 t, %1; cvt.u32.u64 %0, t; }" : "=r"(a) : "l"(p));
    return a;
}
__device__ __forceinline__ uint32_t bf16pack(float x, float y) {
    return ((uint32_t)__bfloat16_as_ushort(__float2bfloat16_rn(y)) << 16)
         |  (uint32_t)__bfloat16_as_ushort(__float2bfloat16_rn(x));
}

template <int W>
__device__ __forceinline__ void ins_top(float (&V)[W], int (&I)[W], float v, int k) {
    if (v > V[W - 1] || (v == V[W - 1] && k < I[W - 1])) {
        V[W - 1] = v; I[W - 1] = k;
#pragma unroll
        for (int q = W - 1; q > 0; --q)
            if (V[q] > V[q - 1] || (V[q] == V[q - 1] && I[q] < I[q - 1])) {
                float tv = V[q]; V[q] = V[q - 1]; V[q - 1] = tv;
                int   ti = I[q]; I[q] = I[q - 1]; I[q - 1] = ti;
            }
    }
}

// ---------------- Stage 0: prep ----------------
__global__ void prep_kernel(const float* __restrict__ cent) {
    int k    = (blockIdx.x * blockDim.x + threadIdx.x) >> 5;   // one warp per centroid
    int lane = threadIdx.x & 31;
    const float4* cr = reinterpret_cast<const float4*>(cent + (size_t)k * DIM);
    float4 a = cr[lane], b = cr[lane + 32];
    double s = (double)a.x * a.x + (double)a.y * a.y + (double)a.z * a.z + (double)a.w * a.w
             + (double)b.x * b.x + (double)b.y * b.y + (double)b.z * b.z + (double)b.w * b.w;
#pragma unroll
    for (int o = 16; o; o >>= 1) s += __shfl_xor_sync(0xffffffffu, s, o);
    if (lane == 0) { g_c2d[k] = s; g_c2[k] = (float)s; }

#pragma unroll
    for (int h = 0; h < 2; ++h) {
        float4 v = h ? b : a;
        uint32_t d0   = h * 128 + lane * 4;
        uint32_t byte = (uint32_t)k * 512u + ((d0 * 2u) ^ (((uint32_t)k & 7u) << 4));
        g_centB[byte >> 3] = ((unsigned long long)bf16pack(v.z, v.w) << 32)
                           | bf16pack(v.x, v.y);
    }
}

// ---------------- Stage 1: HMMA candidate pass ----------------
#define SMEM_A   0                  // 128 x 512B = 65536
#define SMEM_B   65536              // 256 x 512B = 131072
#define SMEM_C2  196608             // 1KB
#define SMEM_CV  197632             // float[128][4][8] = 16KB
#define SMEM_CI  214016             // int  [128][4][8] = 16KB
#define SMEM_TOT 230400
#define SSTRIDE  260                // score row stride (floats), bank-skewed

#define LDSM_X4(r0, r1, r2, r3, a)                                           \
    asm volatile("ldmatrix.sync.aligned.m8n8.x4.shared.b16 {%0,%1,%2,%3}, [%4];" \
        : "=r"(r0), "=r"(r1), "=r"(r2), "=r"(r3) : "r"(a))

#define MMA16816(c, A, B)                                                    \
    asm volatile("mma.sync.aligned.m16n8k16.row.col.f32.bf16.bf16.f32 "      \
        "{%0,%1,%2,%3}, {%4,%5,%6,%7}, {%8,%9}, {%0,%1,%2,%3};"              \
        : "+f"((c)[0]), "+f"((c)[1]), "+f"((c)[2]), "+f"((c)[3])             \
        : "r"((A)[0]), "r"((A)[1]), "r"((A)[2]), "r"((A)[3]),                \
          "r"((B)[0]), "r"((B)[1]))

__global__ __launch_bounds__(512, 1)
void mma_cand_kernel(const float* __restrict__ emb, int N) {
    extern __shared__ char smem[];
    const uint32_t sb = smem_u32(smem);
    const int tid = threadIdx.x, wid = tid >> 5, l = tid & 31;
    const int wm = wid & 3, wn = wid >> 2;      // 4x4 warp grid
    const int n0 = blockIdx.x * 128;

    if (tid < KTOT) ((float*)(smem + SMEM_C2))[tid] = g_c2[tid];

    // B: straight copy of the pre-swizzled bf16 image (L2-resident)
    for (int i = tid; i < 131072 / 16; i += 512)
        ((float4*)(smem + SMEM_B))[i] = reinterpret_cast<const float4*>(g_centB)[i];

    // A: fp32 -> bf16, swizzled [row][k] layout
    for (int idx = tid; idx < 128 * 64; idx += 512) {
        int row = idx >> 6, c4 = idx & 63, gr = n0 + row;
        float4 v = make_float4(0.f, 0.f, 0.f, 0.f);
        if (gr < N) v = reinterpret_cast<const float4*>(emb)[(size_t)gr * 64 + c4];
        uint32_t byte = (uint32_t)row * 512u
                      + (((uint32_t)c4 * 8u) ^ (((uint32_t)row & 7u) << 4));
        *reinterpret_cast<uint2*>(smem + SMEM_A + byte) =
            make_uint2(bf16pack(v.x, v.y), bf16pack(v.z, v.w));
    }
    __syncthreads();

    // per-lane ldmatrix address components
    const uint32_t xa  = ((uint32_t)l & 7u) << 4;                 // swizzle xor
    const uint32_t aro = (uint32_t)(wm * 32 + (l & 7) + (l & 8)); // A row, mt=0
    const uint32_t aof0 = sb + SMEM_A + aro * 512u;
    const uint32_t aof1 = aof0 + 16u * 512u;                      // mt=1
    const uint32_t ka  = (uint32_t)((l >> 4) & 1) * 16u;          // A k-byte half
    const uint32_t nb0 = (uint32_t)(wn * 64 + (l & 7) + ((l >> 4) & 1) * 8);
    uint32_t bof[4];
#pragma unroll
    for (int p = 0; p < 4; ++p) bof[p] = sb + SMEM_B + (nb0 + 16u * p) * 512u;
    const uint32_t kb  = (uint32_t)((l >> 3) & 1) * 16u;          // B k-byte half

    float acc[2][8][4];
#pragma unroll
    for (int mt = 0; mt < 2; ++mt)
#pragma unroll
        for (int nt = 0; nt < 8; ++nt)
#pragma unroll
            for (int q = 0; q < 4; ++q) acc[mt][nt][q] = 0.f;

#pragma unroll
    for (int ks = 0; ks < 16; ++ks) {
        const uint32_t kbyte = (uint32_t)ks * 32u;
        uint32_t af[2][4], bfr[8][2];
        LDSM_X4(af[0][0], af[0][1], af[0][2], af[0][3], aof0 + ((kbyte + ka) ^ xa));
        LDSM_X4(af[1][0], af[1][1], af[1][2], af[1][3], aof1 + ((kbyte + ka) ^ xa));
#pragma unroll
        for (int p = 0; p < 4; ++p) {
            uint32_t addr = bof[p] + ((kbyte + kb) ^ xa);
            LDSM_X4(bfr[2 * p][0], bfr[2 * p][1], bfr[2 * p + 1][0], bfr[2 * p + 1][1], addr);
        }
#pragma unroll
        for (int mt = 0; mt < 2; ++mt)
#pragma unroll
            for (int nt = 0; nt < 8; ++nt)
                MMA16816(acc[mt][nt], af[mt], bfr[nt]);
    }

    __syncthreads();   // all warps done reading A/B; reuse smem for scores

    // scores s = c2 - 2*dot into padded smem [128][SSTRIDE]
    {
        float* sc = (float*)smem;
        const float* c2s = (const float*)(smem + SMEM_C2);
#pragma unroll
        for (int mt = 0; mt < 2; ++mt) {
            int row = wm * 32 + mt * 16 + (l >> 2);
#pragma unroll
            for (int nt = 0; nt < 8; ++nt) {
                int col = wn * 64 + nt * 8 + 2 * (l & 3);
                float c2a = c2s[col], c2b = c2s[col + 1];
                sc[(size_t)row * SSTRIDE + col]           = c2a - 2.f * acc[mt][nt][0];
                sc[(size_t)row * SSTRIDE + col + 1]       = c2b - 2.f * acc[mt][nt][1];
                sc[(size_t)(row + 8) * SSTRIDE + col]     = c2a - 2.f * acc[mt][nt][2];
                sc[(size_t)(row + 8) * SSTRIDE + col + 1] = c2b - 2.f * acc[mt][nt][3];
            }
        }
    }
    __syncthreads();

    // per-row top-8: 4 threads/row each keep top-8 of their 64-col slice
    {
        const float* sc = (const float*)smem;
        int row = tid >> 2, part = tid & 3, k0 = part * 64;
        float V[NC]; int I[NC];
#pragma unroll
        for (int q = 0; q < NC; ++q) { V[q] = -__int_as_float(0x7f800000); I[q] = q; }
#pragma unroll 4
        for (int j = 0; j < 64; ++j)
            ins_top<NC>(V, I, sc[(size_t)row * SSTRIDE + k0 + j], k0 + j);
        float* cv = (float*)(smem + SMEM_CV);
        int*   ci = (int*)(smem + SMEM_CI);
#pragma unroll
        for (int q = 0; q < NC; ++q) {
            cv[(row * 4 + part) * NC + q] = V[q];
            ci[(row * 4 + part) * NC + q] = I[q];
        }
    }
    __syncthreads();

    // merge 32 -> global top-8 per row
    if (tid < 128) {
        int row = tid, gr = n0 + row;
        if (gr < N) {
            const float* cv = (const float*)(smem + SMEM_CV);
            const int*   ci = (const int*)(smem + SMEM_CI);
            float V[NC]; int I[NC];
#pragma unroll
            for (int q = 0; q < NC; ++q) { V[q] = -__int_as_float(0x7f800000); I[q] = q; }
            for (int j = 0; j < 4 * NC; ++j)
                ins_top<NC>(V, I, cv[row * 4 * NC + j], ci[row * 4 * NC + j]);
#pragma unroll
            for (int q = 0; q < NC; ++q) g_cand[(size_t)gr * NC + q] = I[q];
        }
    }
}

// ---------------- Stage 2: exact refine (validated R3, now 8 candidates) ----------------
__device__ __forceinline__ double wred(double v) {
#pragma unroll
    for (int o = 16; o; o >>= 1) v += __shfl_xor_sync(0xffffffffu, v, o);
    return v;
}

__global__ __launch_bounds__(256)
void refine_kernel(const float* __restrict__ emb,
                   const float* __restrict__ cent,
                   float* __restrict__ out, int N) {
    int row  = (blockIdx.x * blockDim.x + threadIdx.x) >> 5;
    int lane = threadIdx.x & 31;
    if (row >= N) return;

    const float4* er = reinterpret_cast<const float4*>(emb + (size_t)row * DIM);
    float4 e0 = er[lane];
    float4 e1 = er[lane + 32];

    double px = (double)e0.x * e0.x + (double)e0.y * e0.y
              + (double)e0.z * e0.z + (double)e0.w * e0.w
              + (double)e1.x * e1.x + (double)e1.y * e1.y
              + (double)e1.z * e1.z + (double)e1.w * e1.w;
    float x2f = (float)wred(px);

    float V1 = -__int_as_float(0x7f800000), V2 = V1;
    int   I1 = 0, I2 = 0;

#pragma unroll
    for (int j = 0; j < NC; ++j) {
        int k = g_cand[(size_t)row * NC + j];
        const float4* cr = reinterpret_cast<const float4*>(cent + (size_t)k * DIM);
        float4 c0 = cr[lane];
        float4 c1 = cr[lane + 32];
        double pd = (double)e0.x * c0.x + (double)e0.y * c0.y
                  + (double)e0.z * c0.z + (double)e0.w * c0.w
                  + (double)e1.x * c1.x + (double)e1.y * c1.y
                  + (double)e1.z * c1.z + (double)e1.w * c1.w;
        float xcf = (float)wred(pd);
        float a = __fadd_rn(x2f, (float)g_c2d[k]);
        float t = __fadd_rn(a, __fmul_rn(-2.0f, xcf));
        float u = fmaxf(t, 0.0f);
        float r = __fsqrt_rn(u);
        bool b1 = (r > V1) || (r == V1 && k < I1);
        bool b2 = (r > V2) || (r == V2 && k < I2);
        if (b1) { V2 = V1; I2 = I1; V1 = r; I1 = k; }
        else if (b2) { V2 = r; I2 = k; }
    }

    const float4* src = reinterpret_cast<const float4*>(cent + (size_t)I2 * DIM);
    float4*       dst = reinterpret_cast<float4*>(out + (size_t)row * DIM);
    dst[lane]      = src[lane];
    dst[lane + 32] = src[lane + 32];
}

extern "C" void kernel_launch(void* const* d_in, const int* in_sizes, int n_in,
                              void* d_out, int out_size) {
    const float* emb  = (const float*)d_in[0];
    const float* cent = (const float*)d_in[1];
    float* out = (float*)d_out;
    int N = in_sizes[0] / DIM;

    cudaFuncSetAttribute(mma_cand_kernel,
                         cudaFuncAttributeMaxDynamicSharedMemorySize, SMEM_TOT);

    prep_kernel<<<KTOT / 8, 256>>>(cent);
    mma_cand_kernel<<<(N + 127) / 128, 512, SMEM_TOT>>>(emb, N);
    refine_kernel<<<((size_t)N * 32 + 255) / 256, 256>>>(emb, cent, out, N);
}

// round 8
// speedup vs baseline: 3.5246x; 3.5246x over previous
#include <cuda_runtime.h>
#include <cuda_bf16.h>
#include <cstdint>

// Stage 0 (prep): c2 per centroid (fp64 internally -> fp32) + bf16 image of
//   centroids in the exact XOR-swizzled smem byte layout used by ldmatrix.
// Stage 1 (HMMA): per CTA of 128 rows, bf16 mma.sync GEMM D[128,256] = A.B^T,
//   s[k] = c2[k] - 2*dot -> per-row top-8 candidate indices.
// Stage 2 (exact): compensated-fp32 (TwoProdFMA + TwoSum, "dot2") dots for the
//   8 candidates -- error ~1e-12 abs vs fp32 bucket 6e-5, so it reproduces the
//   correctly-rounded fp32 chain fl(sqrt(max(fl(fl(x2+c2)-fl(2xc)),0))) that
//   was validated bit-exact in R3/R7, without touching the crippled fp64 pipe
//   (DFMA rt~18.4cyc/SM made the fp64 refine ~2.8ms = the R7 bottleneck).

#define DIM  256
#define KTOT 256
#define NMAX 262144
#define NC   8          // candidates per row

__device__ float  g_c2[KTOT];
__device__ int    g_cand[NMAX * NC];
__device__ unsigned long long g_centB[KTOT * DIM * 2 / 8];   // 128KB bf16 B image

__device__ __forceinline__ uint32_t smem_u32(const void* p) {
    uint32_t a;
    asm("{ .reg .u64 t; cvta.to.shared.u64 t, %1; cvt.u32.u64 %0, t; }" : "=r"(a) : "l"(p));
    return a;
}
__device__ __forceinline__ uint32_t bf16pack(float x, float y) {
    return ((uint32_t)__bfloat16_as_ushort(__float2bfloat16_rn(y)) << 16)
         |  (uint32_t)__bfloat16_as_ushort(__float2bfloat16_rn(x));
}

template <int W>
__device__ __forceinline__ void ins_top(float (&V)[W], int (&I)[W], float v, int k) {
    if (v > V[W - 1] || (v == V[W - 1] && k < I[W - 1])) {
        V[W - 1] = v; I[W - 1] = k;
#pragma unroll
        for (int q = W - 1; q > 0; --q)
            if (V[q] > V[q - 1] || (V[q] == V[q - 1] && I[q] < I[q - 1])) {
                float tv = V[q]; V[q] = V[q - 1]; V[q - 1] = tv;
                int   ti = I[q]; I[q] = I[q - 1]; I[q - 1] = ti;
            }
    }
}

// ---------------- Stage 0: prep ----------------
__global__ void prep_kernel(const float* __restrict__ cent) {
    int k    = (blockIdx.x * blockDim.x + threadIdx.x) >> 5;   // one warp per centroid
    int lane = threadIdx.x & 31;
    const float4* cr = reinterpret_cast<const float4*>(cent + (size_t)k * DIM);
    float4 a = cr[lane], b = cr[lane + 32];
    double s = (double)a.x * a.x + (double)a.y * a.y + (double)a.z * a.z + (double)a.w * a.w
             + (double)b.x * b.x + (double)b.y * b.y + (double)b.z * b.z + (double)b.w * b.w;
#pragma unroll
    for (int o = 16; o; o >>= 1) s += __shfl_xor_sync(0xffffffffu, s, o);
    if (lane == 0) g_c2[k] = (float)s;

#pragma unroll
    for (int h = 0; h < 2; ++h) {
        float4 v = h ? b : a;
        uint32_t d0   = h * 128 + lane * 4;
        uint32_t byte = (uint32_t)k * 512u + ((d0 * 2u) ^ (((uint32_t)k & 7u) << 4));
        g_centB[byte >> 3] = ((unsigned long long)bf16pack(v.z, v.w) << 32)
                           | bf16pack(v.x, v.y);
    }
}

// ---------------- Stage 1: HMMA candidate pass ----------------
#define SMEM_A   0                  // 128 x 512B = 65536
#define SMEM_B   65536              // 256 x 512B = 131072
#define SMEM_C2  196608             // 1KB
#define SMEM_CV  197632             // float[128][4][8] = 16KB
#define SMEM_CI  214016             // int  [128][4][8] = 16KB
#define SMEM_TOT 230400
#define SSTRIDE  260                // score row stride (floats), bank-skewed

#define LDSM_X4(r0, r1, r2, r3, a)                                           \
    asm volatile("ldmatrix.sync.aligned.m8n8.x4.shared.b16 {%0,%1,%2,%3}, [%4];" \
        : "=r"(r0), "=r"(r1), "=r"(r2), "=r"(r3) : "r"(a))

#define MMA16816(c, A, B)                                                    \
    asm volatile("mma.sync.aligned.m16n8k16.row.col.f32.bf16.bf16.f32 "      \
        "{%0,%1,%2,%3}, {%4,%5,%6,%7}, {%8,%9}, {%0,%1,%2,%3};"              \
        : "+f"((c)[0]), "+f"((c)[1]), "+f"((c)[2]), "+f"((c)[3])             \
        : "r"((A)[0]), "r"((A)[1]), "r"((A)[2]), "r"((A)[3]),                \
          "r"((B)[0]), "r"((B)[1]))

__global__ __launch_bounds__(512, 1)
void mma_cand_kernel(const float* __restrict__ emb, int N) {
    extern __shared__ char smem[];
    const uint32_t sb = smem_u32(smem);
    const int tid = threadIdx.x, wid = tid >> 5, l = tid & 31;
    const int wm = wid & 3, wn = wid >> 2;      // 4x4 warp grid
    const int n0 = blockIdx.x * 128;

    if (tid < KTOT) ((float*)(smem + SMEM_C2))[tid] = g_c2[tid];

    // B: straight copy of the pre-swizzled bf16 image (L2-resident)
    for (int i = tid; i < 131072 / 16; i += 512)
        ((float4*)(smem + SMEM_B))[i] = reinterpret_cast<const float4*>(g_centB)[i];

    // A: fp32 -> bf16, swizzled [row][k] layout
    for (int idx = tid; idx < 128 * 64; idx += 512) {
        int row = idx >> 6, c4 = idx & 63, gr = n0 + row;
        float4 v = make_float4(0.f, 0.f, 0.f, 0.f);
        if (gr < N) v = reinterpret_cast<const float4*>(emb)[(size_t)gr * 64 + c4];
        uint32_t byte = (uint32_t)row * 512u
                      + (((uint32_t)c4 * 8u) ^ (((uint32_t)row & 7u) << 4));
        *reinterpret_cast<uint2*>(smem + SMEM_A + byte) =
            make_uint2(bf16pack(v.x, v.y), bf16pack(v.z, v.w));
    }
    __syncthreads();

    const uint32_t xa  = ((uint32_t)l & 7u) << 4;                 // swizzle xor
    const uint32_t aro = (uint32_t)(wm * 32 + (l & 7) + (l & 8)); // A row, mt=0
    const uint32_t aof0 = sb + SMEM_A + aro * 512u;
    const uint32_t aof1 = aof0 + 16u * 512u;                      // mt=1
    const uint32_t ka  = (uint32_t)((l >> 4) & 1) * 16u;          // A k-byte half
    const uint32_t nb0 = (uint32_t)(wn * 64 + (l & 7) + ((l >> 4) & 1) * 8);
    uint32_t bof[4];
#pragma unroll
    for (int p = 0; p < 4; ++p) bof[p] = sb + SMEM_B + (nb0 + 16u * p) * 512u;
    const uint32_t kb  = (uint32_t)((l >> 3) & 1) * 16u;          // B k-byte half

    float acc[2][8][4];
#pragma unroll
    for (int mt = 0; mt < 2; ++mt)
#pragma unroll
        for (int nt = 0; nt < 8; ++nt)
#pragma unroll
            for (int q = 0; q < 4; ++q) acc[mt][nt][q] = 0.f;

#pragma unroll
    for (int ks = 0; ks < 16; ++ks) {
        const uint32_t kbyte = (uint32_t)ks * 32u;
        uint32_t af[2][4], bfr[8][2];
        LDSM_X4(af[0][0], af[0][1], af[0][2], af[0][3], aof0 + ((kbyte + ka) ^ xa));
        LDSM_X4(af[1][0], af[1][1], af[1][2], af[1][3], aof1 + ((kbyte + ka) ^ xa));
#pragma unroll
        for (int p = 0; p < 4; ++p) {
            uint32_t addr = bof[p] + ((kbyte + kb) ^ xa);
            LDSM_X4(bfr[2 * p][0], bfr[2 * p][1], bfr[2 * p + 1][0], bfr[2 * p + 1][1], addr);
        }
#pragma unroll
        for (int mt = 0; mt < 2; ++mt)
#pragma unroll
            for (int nt = 0; nt < 8; ++nt)
                MMA16816(acc[mt][nt], af[mt], bfr[nt]);
    }

    __syncthreads();   // all warps done reading A/B; reuse smem for scores

    {
        float* sc = (float*)smem;
        const float* c2s = (const float*)(smem + SMEM_C2);
#pragma unroll
        for (int mt = 0; mt < 2; ++mt) {
            int row = wm * 32 + mt * 16 + (l >> 2);
#pragma unroll
            for (int nt = 0; nt < 8; ++nt) {
                int col = wn * 64 + nt * 8 + 2 * (l & 3);
                float c2a = c2s[col], c2b = c2s[col + 1];
                sc[(size_t)row * SSTRIDE + col]           = c2a - 2.f * acc[mt][nt][0];
                sc[(size_t)row * SSTRIDE + col + 1]       = c2b - 2.f * acc[mt][nt][1];
                sc[(size_t)(row + 8) * SSTRIDE + col]     = c2a - 2.f * acc[mt][nt][2];
                sc[(size_t)(row + 8) * SSTRIDE + col + 1] = c2b - 2.f * acc[mt][nt][3];
            }
        }
    }
    __syncthreads();

    {
        const float* sc = (const float*)smem;
        int row = tid >> 2, part = tid & 3, k0 = part * 64;
        float V[NC]; int I[NC];
#pragma unroll
        for (int q = 0; q < NC; ++q) { V[q] = -__int_as_float(0x7f800000); I[q] = q; }
#pragma unroll 4
        for (int j = 0; j < 64; ++j)
            ins_top<NC>(V, I, sc[(size_t)row * SSTRIDE + k0 + j], k0 + j);
        float* cv = (float*)(smem + SMEM_CV);
        int*   ci = (int*)(smem + SMEM_CI);
#pragma unroll
        for (int q = 0; q < NC; ++q) {
            cv[(row * 4 + part) * NC + q] = V[q];
            ci[(row * 4 + part) * NC + q] = I[q];
        }
    }
    __syncthreads();

    if (tid < 128) {
        int row = tid, gr = n0 + row;
        if (gr < N) {
            const float* cv = (const float*)(smem + SMEM_CV);
            const int*   ci = (const int*)(smem + SMEM_CI);
            float V[NC]; int I[NC];
#pragma unroll
            for (int q = 0; q < NC; ++q) { V[q] = -__int_as_float(0x7f800000); I[q] = q; }
            for (int j = 0; j < 4 * NC; ++j)
                ins_top<NC>(V, I, cv[row * 4 * NC + j], ci[row * 4 * NC + j]);
#pragma unroll
            for (int q = 0; q < NC; ++q) g_cand[(size_t)gr * NC + q] = I[q];
        }
    }
}

// ---------------- Stage 2: compensated-fp32 exact refine ----------------
// TwoSum (Knuth, branchless, 6 flops)
__device__ __forceinline__ void two_sum(float a, float b, float& s, float& e) {
    s = a + b;
    float bp = s - a;
    e = (a - (s - bp)) + (b - bp);
}
// accumulate a*b into compensated pair (s,c): TwoProdFMA + TwoSum
__device__ __forceinline__ void dot_acc(float a, float b, float& s, float& c) {
    float p = a * b;
    float e = fmaf(a, b, -p);
    float t, e2;
    two_sum(s, p, t, e2);
    s = t;
    c += (e + e2);
}
// warp-reduce a compensated pair; returns fl(sum)
__device__ __forceinline__ float wred_df(float s, float c) {
#pragma unroll
    for (int o = 16; o; o >>= 1) {
        float so = __shfl_xor_sync(0xffffffffu, s, o);
        float co = __shfl_xor_sync(0xffffffffu, c, o);
        float t, e;
        two_sum(s, so, t, e);
        s = t;
        c += (co + e);
    }
    return s + c;
}

__global__ __launch_bounds__(256)
void refine_kernel(const float* __restrict__ emb,
                   const float* __restrict__ cent,
                   float* __restrict__ out, int N) {
    int row  = (blockIdx.x * blockDim.x + threadIdx.x) >> 5;
    int lane = threadIdx.x & 31;
    if (row >= N) return;

    const float4* er = reinterpret_cast<const float4*>(emb + (size_t)row * DIM);
    float4 e0 = er[lane];
    float4 e1 = er[lane + 32];

    float xs = 0.f, xc = 0.f;
    dot_acc(e0.x, e0.x, xs, xc); dot_acc(e0.y, e0.y, xs, xc);
    dot_acc(e0.z, e0.z, xs, xc); dot_acc(e0.w, e0.w, xs, xc);
    dot_acc(e1.x, e1.x, xs, xc); dot_acc(e1.y, e1.y, xs, xc);
    dot_acc(e1.z, e1.z, xs, xc); dot_acc(e1.w, e1.w, xs, xc);
    float x2f = wred_df(xs, xc);

    float V1 = -__int_as_float(0x7f800000), V2 = V1;
    int   I1 = 0, I2 = 0;

#pragma unroll
    for (int j = 0; j < NC; ++j) {
        int k = g_cand[(size_t)row * NC + j];
        const float4* cr = reinterpret_cast<const float4*>(cent + (size_t)k * DIM);
        float4 c0 = cr[lane];
        float4 c1 = cr[lane + 32];
        float ds = 0.f, dc = 0.f;
        dot_acc(e0.x, c0.x, ds, dc); dot_acc(e0.y, c0.y, ds, dc);
        dot_acc(e0.z, c0.z, ds, dc); dot_acc(e0.w, c0.w, ds, dc);
        dot_acc(e1.x, c1.x, ds, dc); dot_acc(e1.y, c1.y, ds, dc);
        dot_acc(e1.z, c1.z, ds, dc); dot_acc(e1.w, c1.w, ds, dc);
        float xcf = wred_df(ds, dc);                  // correctly-rounded dot
        // reference chain: ((x2 + c2) - 2*xc) -> max(,0) -> sqrt, all fp32 rn
        float a = __fadd_rn(x2f, g_c2[k]);
        float t = __fadd_rn(a, __fmul_rn(-2.0f, xcf));
        float u = fmaxf(t, 0.0f);
        float r = __fsqrt_rn(u);
        bool b1 = (r > V1) || (r == V1 && k < I1);
        bool b2 = (r > V2) || (r == V2 && k < I2);
        if (b1) { V2 = V1; I2 = I1; V1 = r; I1 = k; }
        else if (b2) { V2 = r; I2 = k; }
    }

    const float4* src = reinterpret_cast<const float4*>(cent + (size_t)I2 * DIM);
    float4*       dst = reinterpret_cast<float4*>(out + (size_t)row * DIM);
    dst[lane]      = src[lane];
    dst[lane + 32] = src[lane + 32];
}

extern "C" void kernel_launch(void* const* d_in, const int* in_sizes, int n_in,
                              void* d_out, int out_size) {
    const float* emb  = (const float*)d_in[0];
    const float* cent = (const float*)d_in[1];
    float* out = (float*)d_out;
    int N = in_sizes[0] / DIM;

    cudaFuncSetAttribute(mma_cand_kernel,
                         cudaFuncAttributeMaxDynamicSharedMemorySize, SMEM_TOT);

    prep_kernel<<<KTOT / 8, 256>>>(cent);
    mma_cand_kernel<<<(N + 127) / 128, 512, SMEM_TOT>>>(emb, N);
    refine_kernel<<<((size_t)N * 32 + 255) / 256, 256>>>(emb, cent, out, N);
}